// round 2
// baseline (speedup 1.0000x reference)
#include <cuda_runtime.h>

#define NN 32
#define CC 1024
#define NT 1024

// dynamic smem layout
#define OFF_ROWS 0                      // float [32][1024]  = 131072 B
#define OFF_D    131072                 // float [32][32]    = 4096 B
#define OFF_SQ   135168                 // double[32]        = 256 B
#define OFF_RED  135424                 // u64   [32]        = 256 B
#define OFF_DRED 135680                 // double[32]        = 256 B
#define OFF_L    135936                 // int   [32]        = 128 B
#define SMEM_TOTAL 136064

__global__ __launch_bounds__(NT, 1)
void merge_tree_kernel(const float* __restrict__ x,
                       const float* __restrict__ cw,
                       const float* __restrict__ cb,
                       float* __restrict__ out)
{
    extern __shared__ unsigned char sm_raw[];
    float*  rows = (float*)(sm_raw + OFF_ROWS);
    float*  D    = (float*)(sm_raw + OFF_D);
    double* sq   = (double*)(sm_raw + OFF_SQ);
    unsigned long long* red = (unsigned long long*)(sm_raw + OFF_RED);
    double* dred = (double*)(sm_raw + OFF_DRED);
    int*    L    = (int*)(sm_raw + OFF_L);

    const int tid  = threadIdx.x;
    const int lane = tid & 31;
    const int warp = tid >> 5;
    const int b    = blockIdx.x;

    // ---- load batch rows into smem (coalesced float4) ----
    {
        const float4* xb4 = (const float4*)(x + (size_t)b * (NN * CC));
        float4* r4 = (float4*)rows;
        #pragma unroll
        for (int i = tid; i < NN * CC / 4; i += NT) r4[i] = xb4[i];
    }
    const float w00 = cw[0], w01 = cw[1], w02 = cw[2];
    const float w10 = cw[3], w11 = cw[4], w12 = cw[5];
    const float bv  = cb[0];
    if (tid < NN) L[tid] = tid;
    __syncthreads();

    // ---- squared norms (fp64), warp per slot ----
    {
        const float4* r = (const float4*)(rows + warp * CC);
        double a0 = 0, a1 = 0, a2 = 0, a3 = 0;
        #pragma unroll
        for (int k = 0; k < 8; k++) {
            float4 v = r[lane + 32 * k];
            a0 = fma((double)v.x, (double)v.x, a0);
            a1 = fma((double)v.y, (double)v.y, a1);
            a2 = fma((double)v.z, (double)v.z, a2);
            a3 = fma((double)v.w, (double)v.w, a3);
        }
        double acc = (a0 + a1) + (a2 + a3);
        #pragma unroll
        for (int o = 16; o; o >>= 1) acc += __shfl_down_sync(0xffffffffu, acc, o);
        if (!lane) sq[warp] = acc;
    }
    __syncthreads();

    // ---- initial full distance matrix: 496 pairs, warp per pair ----
    for (int p = warp; p < NN * (NN - 1) / 2; p += 32) {
        int i = 0, rem = p;
        while (rem >= NN - 1 - i) { rem -= NN - 1 - i; i++; }
        int j = i + 1 + rem;
        const float4* ri = (const float4*)(rows + i * CC);
        const float4* rj = (const float4*)(rows + j * CC);
        double a0 = 0, a1 = 0, a2 = 0, a3 = 0;
        #pragma unroll
        for (int k = 0; k < 8; k++) {
            float4 u = ri[lane + 32 * k];
            float4 v = rj[lane + 32 * k];
            a0 = fma((double)u.x, (double)v.x, a0);
            a1 = fma((double)u.y, (double)v.y, a1);
            a2 = fma((double)u.z, (double)v.z, a2);
            a3 = fma((double)u.w, (double)v.w, a3);
        }
        double acc = (a0 + a1) + (a2 + a3);
        #pragma unroll
        for (int o = 16; o; o >>= 1) acc += __shfl_down_sync(0xffffffffu, acc, o);
        if (!lane) {
            double d2 = sq[i] + sq[j] - 2.0 * acc;
            float f = (float)d2; if (f < 0.f) f = 0.f;
            float d = sqrtf(f);
            D[i * NN + j] = d;
            D[j * NN + i] = d;
        }
    }
    __syncthreads();

    // ---- 31 merge steps ----
    int n = NN;
    for (int step = 0; step < NN - 1; step++, n--) {
        // argmin over logical pairs (i<j), value D[L[i]][L[j]],
        // tie-break lexicographic (i,j) == reference row-major first occurrence
        unsigned long long best = 0xffffffffffffffffull;
        const int npairs = n * (n - 1) / 2;
        for (int p = tid; p < npairs; p += NT) {
            int i = 0, rem = p;
            while (rem >= n - 1 - i) { rem -= n - 1 - i; i++; }
            int j = i + 1 + rem;
            float d = D[L[i] * NN + L[j]];
            unsigned long long key =
                ((unsigned long long)__float_as_uint(d) << 32) |
                (unsigned)(i * NN + j);
            best = min(best, key);
        }
        #pragma unroll
        for (int o = 16; o; o >>= 1) {
            unsigned long long t = __shfl_down_sync(0xffffffffu, best, o);
            best = min(best, t);
        }
        if (!lane) red[warp] = best;
        __syncthreads();
        if (warp == 0) {
            unsigned long long v = red[lane];
            #pragma unroll
            for (int o = 16; o; o >>= 1) {
                unsigned long long t = __shfl_down_sync(0xffffffffu, v, o);
                v = min(v, t);
            }
            if (!lane) red[0] = v;
        }
        __syncthreads();
        const unsigned key = (unsigned)red[0];
        const int a   = (key >> 5) & 31;
        const int bbj = key & 31;
        const int ra  = L[a];
        const int rb  = L[bbj];
        const int dst = L[(a == 1) ? 0 : a];   // freed slot takes the merged row

        // conv1d(2ch -> 1ch, k=3, SAME) + bias + relu, one element per thread
        const float* Xa = rows + ra * CC;
        const float* Xb = rows + rb * CC;
        const int h = tid;
        float a1v = Xa[h], b1v = Xb[h];
        float a0v = (h > 0)      ? Xa[h - 1] : 0.f;
        float a2v = (h < CC - 1) ? Xa[h + 1] : 0.f;
        float b0v = (h > 0)      ? Xb[h - 1] : 0.f;
        float b2v = (h < CC - 1) ? Xb[h + 1] : 0.f;
        float m = fmaf(w00, a0v, fmaf(w01, a1v, fmaf(w02, a2v,
                  fmaf(w10, b0v, fmaf(w11, b1v, fmaf(w12, b2v, bv))))));
        m = fmaxf(m, 0.f);

        // new logical->slot map (computed from old L before modification)
        int newv = 0;
        if (tid < n - 1) {
            if (tid == 0) newv = dst;
            else {
                int pp = tid + 1;
                int src = (pp == a) ? 0 : ((pp == bbj) ? 1 : pp);
                newv = L[src];
            }
        }
        __syncthreads();                 // all reads of rows[ra]/rows[rb]/L done
        rows[dst * CC + h] = m;
        if (tid < n - 1) L[tid] = newv;

        // squared norm of merged row (block reduce fp64)
        double p2 = (double)m * (double)m;
        #pragma unroll
        for (int o = 16; o; o >>= 1) p2 += __shfl_down_sync(0xffffffffu, p2, o);
        if (!lane) dred[warp] = p2;
        __syncthreads();
        if (tid == 0) {
            double s = 0;
            #pragma unroll
            for (int q = 0; q < 32; q++) s += dred[q];
            sq[dst] = s;
        }
        __syncthreads();

        // dots: merged row vs each survivor, warp per survivor
        const int cnt = n - 2;           // survivors (new logical 1..n-2)
        if (warp < cnt) {
            int s = L[1 + warp];
            const float4* rm = (const float4*)(rows + dst * CC);
            const float4* rs = (const float4*)(rows + s * CC);
            double A0 = 0, A1 = 0, A2 = 0, A3 = 0;
            #pragma unroll
            for (int k = 0; k < 8; k++) {
                float4 u = rm[lane + 32 * k];
                float4 v = rs[lane + 32 * k];
                A0 = fma((double)u.x, (double)v.x, A0);
                A1 = fma((double)u.y, (double)v.y, A1);
                A2 = fma((double)u.z, (double)v.z, A2);
                A3 = fma((double)u.w, (double)v.w, A3);
            }
            double acc = (A0 + A1) + (A2 + A3);
            #pragma unroll
            for (int o = 16; o; o >>= 1) acc += __shfl_down_sync(0xffffffffu, acc, o);
            if (!lane) {
                double d2 = sq[dst] + sq[s] - 2.0 * acc;
                float f = (float)d2; if (f < 0.f) f = 0.f;
                float d = sqrtf(f);
                D[dst * NN + s] = d;
                D[s * NN + dst] = d;
            }
        }
        __syncthreads();
    }

    // final merged row is at L[0]
    out[(size_t)b * CC + tid] = rows[L[0] * CC + tid];
}

extern "C" void kernel_launch(void* const* d_in, const int* in_sizes, int n_in,
                              void* d_out, int out_size)
{
    const float* x  = (const float*)d_in[0];
    const float* cw = (const float*)d_in[1];
    const float* cb = (const float*)d_in[2];
    float* out = (float*)d_out;

    int B = in_sizes[0] / (NN * CC);

    cudaFuncSetAttribute(merge_tree_kernel,
                         cudaFuncAttributeMaxDynamicSharedMemorySize,
                         SMEM_TOTAL);
    merge_tree_kernel<<<B, NT, SMEM_TOTAL>>>(x, cw, cb, out);
}

// round 3
// speedup vs baseline: 15.9889x; 15.9889x over previous
#include <cuda_runtime.h>

#define NN 32
#define CC 1024
#define NT 1024

// dynamic smem layout (16B-aligned blocks)
#define OFF_ROWS 0                      // float [32][1024]  = 131072
#define OFF_D    131072                 // float [32][32]    = 4096
#define OFF_RED  135168                 // u64   [32]        = 256
#define OFF_SQ   135424                 // float [32]        = 128
#define OFF_FRED 135552                 // float [32]        = 128
#define OFF_DOT  135680                 // float [32]        = 128
#define OFF_L    135808                 // int   [32]        = 128
#define SMEM_TOTAL 135936

__device__ __forceinline__ float warp_sum(float v) {
    #pragma unroll
    for (int o = 16; o; o >>= 1) v += __shfl_down_sync(0xffffffffu, v, o);
    return v;
}

__global__ __launch_bounds__(NT, 1)
void merge_tree_kernel(const float* __restrict__ x,
                       const float* __restrict__ cw,
                       const float* __restrict__ cb,
                       float* __restrict__ out)
{
    extern __shared__ unsigned char sm_raw[];
    float*  rows = (float*)(sm_raw + OFF_ROWS);
    float*  D    = (float*)(sm_raw + OFF_D);
    unsigned long long* red = (unsigned long long*)(sm_raw + OFF_RED);
    float*  sq   = (float*)(sm_raw + OFF_SQ);
    float*  fred = (float*)(sm_raw + OFF_FRED);
    float*  dotb = (float*)(sm_raw + OFF_DOT);
    int*    L    = (int*)(sm_raw + OFF_L);

    const int tid  = threadIdx.x;
    const int lane = tid & 31;
    const int warp = tid >> 5;
    const int b    = blockIdx.x;

    // ---- load batch rows into smem (coalesced float4) ----
    {
        const float4* xb4 = (const float4*)(x + (size_t)b * (NN * CC));
        float4* r4 = (float4*)rows;
        #pragma unroll
        for (int i = tid; i < NN * CC / 4; i += NT) r4[i] = xb4[i];
    }
    const float w00 = cw[0], w01 = cw[1], w02 = cw[2];
    const float w10 = cw[3], w11 = cw[4], w12 = cw[5];
    const float bv  = cb[0];
    if (tid < NN) L[tid] = tid;
    __syncthreads();

    // ---- cache own row in registers; norms (fp32 tree-reduce) ----
    float4 rv[8];
    {
        const float4* r4w = (const float4*)(rows + warp * CC);
        #pragma unroll
        for (int k = 0; k < 8; k++) rv[k] = r4w[lane + 32 * k];
        float a0 = 0, a1 = 0, a2 = 0, a3 = 0;
        #pragma unroll
        for (int k = 0; k < 8; k++) {
            a0 = fmaf(rv[k].x, rv[k].x, a0);
            a1 = fmaf(rv[k].y, rv[k].y, a1);
            a2 = fmaf(rv[k].z, rv[k].z, a2);
            a3 = fmaf(rv[k].w, rv[k].w, a3);
        }
        float s = warp_sum((a0 + a1) + (a2 + a3));
        if (!lane) sq[warp] = s;
    }
    __syncthreads();

    // ---- initial gram: warp i vs all j>i, row i register-cached ----
    {
        const float sqi = sq[warp];
        for (int j = warp + 1; j < NN; j++) {
            const float4* rj4 = (const float4*)(rows + j * CC);
            float a0 = 0, a1 = 0, a2 = 0, a3 = 0;
            #pragma unroll
            for (int k = 0; k < 8; k++) {
                float4 v = rj4[lane + 32 * k];
                a0 = fmaf(rv[k].x, v.x, a0);
                a1 = fmaf(rv[k].y, v.y, a1);
                a2 = fmaf(rv[k].z, v.z, a2);
                a3 = fmaf(rv[k].w, v.w, a3);
            }
            float dot = warp_sum((a0 + a1) + (a2 + a3));
            if (!lane) {
                float d2 = sqi + sq[j] - 2.0f * dot;
                float d  = sqrtf(fmaxf(d2, 0.f));
                D[warp * NN + j] = d;
                D[j * NN + warp] = d;
            }
        }
    }
    __syncthreads();

    // ---- 31 merge steps ----
    int n = NN;
    const int pi = tid >> 5;      // argmin pair: i = warp, j = lane
    const int pj = tid & 31;
    for (int step = 0; step < NN - 1; step++, n--) {
        // -- argmin over logical pairs (i<j<n), tie-break lexicographic --
        unsigned long long key = 0xffffffffffffffffull;
        if (pi < pj && pj < n) {
            float d = D[L[pi] * NN + L[pj]];
            key = ((unsigned long long)__float_as_uint(d) << 32)
                | (unsigned)((pi << 5) | pj);
        }
        #pragma unroll
        for (int o = 16; o; o >>= 1) {
            unsigned long long t = __shfl_down_sync(0xffffffffu, key, o);
            key = min(key, t);
        }
        if (!lane) red[warp] = key;
        __syncthreads();
        if (warp == 0) {
            unsigned long long v = red[lane];
            #pragma unroll
            for (int o = 16; o; o >>= 1) {
                unsigned long long t = __shfl_down_sync(0xffffffffu, v, o);
                v = min(v, t);
            }
            if (!lane) red[0] = v;
        }
        __syncthreads();
        const unsigned k32 = (unsigned)red[0];
        const int a   = (k32 >> 5) & 31;
        const int bbj = k32 & 31;
        const int ra  = L[a];
        const int rb  = L[bbj];
        const int dst = L[(a == 1) ? 0 : a];   // freed slot hosts merged row

        // -- conv1d(2ch->1ch, k=3, SAME) + bias + relu, one elem/thread --
        const float* Xa = rows + ra * CC;
        const float* Xb = rows + rb * CC;
        const int h = tid;
        float a1v = Xa[h], b1v = Xb[h];
        float a0v = (h > 0)      ? Xa[h - 1] : 0.f;
        float a2v = (h < CC - 1) ? Xa[h + 1] : 0.f;
        float b0v = (h > 0)      ? Xb[h - 1] : 0.f;
        float b2v = (h < CC - 1) ? Xb[h + 1] : 0.f;
        float m = fmaf(w00, a0v, fmaf(w01, a1v, fmaf(w02, a2v,
                  fmaf(w10, b0v, fmaf(w11, b1v, fmaf(w12, b2v, bv))))));
        m = fmaxf(m, 0.f);

        // new logical->slot map from OLD L
        int newv = 0;
        if (tid < n - 1) {
            if (tid == 0) newv = dst;
            else {
                int pp  = tid + 1;
                int src = (pp == a) ? 0 : ((pp == bbj) ? 1 : pp);
                newv = L[src];
            }
        }
        __syncthreads();                 // all reads of rows/L complete

        rows[dst * CC + h] = m;
        if (tid < n - 1) L[tid] = newv;
        float p2 = warp_sum(m * m);
        if (!lane) fred[warp] = p2;
        __syncthreads();                 // merged row, L, fred visible

        // -- warp 31 finalizes norm; warps 0..cnt-1 do survivor dots --
        const int cnt = n - 2;           // survivors = new logical 1..n-2
        if (warp == 31) {
            float s = fred[lane];
            s = warp_sum(s);
            if (!lane) sq[dst] = s;
        } else if (warp < cnt) {
            const int s = L[1 + warp];
            const float4* rm = (const float4*)(rows + dst * CC);
            const float4* rs = (const float4*)(rows + s * CC);
            float A0 = 0, A1 = 0, A2 = 0, A3 = 0;
            #pragma unroll
            for (int k = 0; k < 8; k++) {
                float4 u = rm[lane + 32 * k];
                float4 v = rs[lane + 32 * k];
                A0 = fmaf(u.x, v.x, A0);
                A1 = fmaf(u.y, v.y, A1);
                A2 = fmaf(u.z, v.z, A2);
                A3 = fmaf(u.w, v.w, A3);
            }
            float dot = warp_sum((A0 + A1) + (A2 + A3));
            if (!lane) dotb[warp] = dot;
        }
        __syncthreads();                 // sq[dst], dotb visible

        if (tid < cnt) {
            const int s = L[1 + tid];
            float d2 = sq[dst] + sq[s] - 2.0f * dotb[tid];
            float d  = sqrtf(fmaxf(d2, 0.f));
            D[dst * NN + s] = d;
            D[s * NN + dst] = d;
        }
        __syncthreads();                 // D ready for next argmin
    }

    // final merged row lives at slot L[0]
    out[(size_t)b * CC + tid] = rows[L[0] * CC + tid];
}

extern "C" void kernel_launch(void* const* d_in, const int* in_sizes, int n_in,
                              void* d_out, int out_size)
{
    const float* x  = (const float*)d_in[0];
    const float* cw = (const float*)d_in[1];
    const float* cb = (const float*)d_in[2];
    float* out = (float*)d_out;

    int B = in_sizes[0] / (NN * CC);

    cudaFuncSetAttribute(merge_tree_kernel,
                         cudaFuncAttributeMaxDynamicSharedMemorySize,
                         SMEM_TOTAL);
    merge_tree_kernel<<<B, NT, SMEM_TOTAL>>>(x, cw, cb, out);
}